// round 4
// baseline (speedup 1.0000x reference)
#include <cuda_runtime.h>
#include <cuda_bf16.h>

// Problem shapes (fixed by dataset)
#define KK 2048   // batch/k dim
#define MM 512    // feature dim m
#define NN 64     // target dim n
#define EPSV 1e-8f
#define LMAX 32
#define ROWS 8    // k-rows per block in fused kernel

// ---------------- scratch (static device global; no allocation) ----------------
__device__ float g_hard[MM * NN];  // scores_hard

// ---------------- Kernel 1: per-column top-l threshold + hard scores ----------
// 64 blocks (one per n-column) x 32 threads.
__global__ __launch_bounds__(32) void hard_kernel(const float* __restrict__ wb,
                                                  const int* __restrict__ lptr,
                                                  float* __restrict__ out_hard) {
    const int n    = blockIdx.x;
    const int lane = threadIdx.x;
    int l = lptr ? *lptr : 8;
    if (l < 1) l = 1;
    if (l > LMAX) l = LMAX;

    float v[16];
#pragma unroll
    for (int i = 0; i < 16; i++)
        v[i] = wb[(lane * 16 + i) * NN + n];

    float top[LMAX];
    for (int i = 0; i < l; i++) top[i] = -3.4e38f;
#pragma unroll
    for (int i = 0; i < 16; i++) {
        float x = v[i];
        if (x > top[l - 1]) {
            int j = l - 1;
            while (j > 0 && top[j - 1] < x) { top[j] = top[j - 1]; j--; }
            top[j] = x;
        }
    }

    int ptr = 0;
    float thr = -3.4e38f;
    for (int r = 0; r < l; r++) {
        float cand = (ptr < l) ? top[ptr] : -3.4e38f;
        float m = cand;
#pragma unroll
        for (int off = 16; off > 0; off >>= 1)
            m = fmaxf(m, __shfl_xor_sync(0xffffffffu, m, off));
        unsigned b = __ballot_sync(0xffffffffu, cand == m);
        int src = __ffs(b) - 1;
        if (lane == src) ptr++;
        thr = m;
    }

#pragma unroll
    for (int i = 0; i < 16; i++) {
        float sh = v[i] - thr + EPSV;
        sh = fminf(fmaxf(sh, -1.f), 1.f);
        float h = (sh + 1.f) * 0.5f;
        int m = lane * 16 + i;
        g_hard[m * NN + n] = h;
        if (out_hard) out_hard[m * NN + n] = h;
    }
}

// ---------------- Kernel 2: fused GEMM + softmax + epilogue ----------------
// Each block owns 8 k-rows. 256 threads: warp w == row w; lane c owns
// columns {4c+128j, j=0..3} (16 accumulators, conflict-free LDS.128).
// Phase 1: S = x @ w_att for the 8x512 strip (x rows cached in smem).
// Phase 2: warp-shuffle softmax, soft kept in smem, written to out_soft.
// Phase 3: stream out & mask_weight (4MB per block), R2-proven geometry.
__global__ __launch_bounds__(256) void fused_kernel(const float* __restrict__ x,
                                                    const float* __restrict__ watt,
                                                    float* __restrict__ out_soft,
                                                    float* __restrict__ out,
                                                    float* __restrict__ mw) {
    __shared__ float xs[ROWS][MM];       // 16 KB: x rows (GEMM A + epilogue xv)
    __shared__ float Bs[16][MM];         // 32 KB: w_att tile; reused as soft_s

    const int t  = threadIdx.x;
    const int r  = t >> 5;     // 0..7  (warp == row)
    const int c  = t & 31;     // lane
    const int k0 = blockIdx.x * ROWS;

    // ---- load x rows into smem (4096 floats = 4 float4 per thread) ----
#pragma unroll
    for (int i = 0; i < 4; i++) {
        int fid  = t + 256 * i;          // 0..1023
        int row  = fid >> 7;             // 0..7
        int col4 = (fid & 127) << 2;     // 0..508
        *(float4*)&xs[row][col4] =
            *(const float4*)&x[(size_t)(k0 + row) * MM + col4];
    }
    __syncthreads();

    // ---- GEMM: acc[j][0..3] covers cols 4c+128j ----
    float4 acc[4];
#pragma unroll
    for (int j = 0; j < 4; j++) acc[j] = make_float4(0.f, 0.f, 0.f, 0.f);

    for (int kt = 0; kt < MM; kt += 16) {
        // load 16x512 w_att tile (8 float4 per thread, coalesced)
#pragma unroll
        for (int i = 0; i < 8; i++) {
            int fid  = t + 256 * i;      // 0..2047
            int brow = fid >> 7;         // 0..15
            int bc4  = (fid & 127) << 2;
            *(float4*)&Bs[brow][bc4] =
                *(const float4*)&watt[(size_t)(kt + brow) * MM + bc4];
        }
        __syncthreads();

#pragma unroll
        for (int kk = 0; kk < 16; kk++) {
            float a = xs[r][kt + kk];    // warp broadcast
#pragma unroll
            for (int j = 0; j < 4; j++) {
                float4 b = *(const float4*)&Bs[kk][(c << 2) + 128 * j];
                acc[j].x += a * b.x;
                acc[j].y += a * b.y;
                acc[j].z += a * b.z;
                acc[j].w += a * b.w;
            }
        }
        __syncthreads();
    }

    // ---- softmax over the 512 cols of row r (warp-wide) ----
    float mx = -3.4e38f;
#pragma unroll
    for (int j = 0; j < 4; j++) {
        mx = fmaxf(mx, fmaxf(fmaxf(acc[j].x, acc[j].y), fmaxf(acc[j].z, acc[j].w)));
    }
#pragma unroll
    for (int off = 16; off > 0; off >>= 1)
        mx = fmaxf(mx, __shfl_xor_sync(0xffffffffu, mx, off));

    float sum = 0.f;
#pragma unroll
    for (int j = 0; j < 4; j++) {
        acc[j].x = __expf(acc[j].x - mx);
        acc[j].y = __expf(acc[j].y - mx);
        acc[j].z = __expf(acc[j].z - mx);
        acc[j].w = __expf(acc[j].w - mx);
        sum += acc[j].x + acc[j].y + acc[j].z + acc[j].w;
    }
#pragma unroll
    for (int off = 16; off > 0; off >>= 1)
        sum += __shfl_xor_sync(0xffffffffu, sum, off);
    float inv = 1.f / sum;

    // soft values -> smem (reuse Bs) and out_soft
    float* soft_s = &Bs[0][0];           // [ROWS][MM] alias
#pragma unroll
    for (int j = 0; j < 4; j++) {
        float4 s4 = make_float4(acc[j].x * inv + EPSV, acc[j].y * inv + EPSV,
                                acc[j].z * inv + EPSV, acc[j].w * inv + EPSV);
        int col = (c << 2) + 128 * j;
        *(float4*)&soft_s[r * MM + col] = s4;
        if (out_soft)
            *(float4*)&out_soft[(size_t)(k0 + r) * MM + col] = s4;
    }
    __syncthreads();

    // ---- epilogue: 8 rows x 512 m x 16 n4-chunks = 65536 float4-pairs ----
    // 256 iters/thread; per iter: 1 float4 to out + 1 to mw (R2 geometry).
#pragma unroll 4
    for (int it = 0; it < 256; it++) {
        int id  = it * 256 + t;          // 0..65535
        int n4  = (id & 15) << 2;        // 0,4,..,60
        int kml = id >> 4;               // 0..4095
        int m   = kml & (MM - 1);
        int rr  = kml >> 9;

        float ss = soft_s[rr * MM + m];  // LDS broadcast
        float xv = xs[rr][m];            // LDS broadcast
        float4 h = __ldg((const float4*)(g_hard + m * NN + n4));

        float4 mw4 = make_float4(h.x * ss, h.y * ss, h.z * ss, h.w * ss);
        float4 o4  = make_float4(mw4.x * xv, mw4.y * xv, mw4.z * xv, mw4.w * xv);

        size_t base = ((size_t)(k0 + rr) * MM + m) * NN + n4;
        *(float4*)&out[base] = o4;
        if (mw) *(float4*)&mw[base] = mw4;
    }
}

// ---------------- launch ----------------
extern "C" void kernel_launch(void* const* d_in, const int* in_sizes, int n_in,
                              void* d_out, int out_size) {
    const float* x     = (const float*)d_in[0];
    const float* w_att = (const float*)d_in[1];
    const float* w_b   = (const float*)d_in[2];
    const int*   lptr  = (n_in > 3) ? (const int*)d_in[3] : nullptr;

    const long SZ_OUT  = (long)KK * MM * NN;
    const long SZ_HARD = (long)MM * NN;
    const long SZ_SOFT = (long)KK * MM;

    float* out_ptr  = (float*)d_out;
    float* hard_ptr = nullptr;
    float* soft_ptr = nullptr;
    float* mw_ptr   = nullptr;
    if ((long)out_size >= SZ_OUT + SZ_HARD + SZ_SOFT + SZ_OUT) {
        hard_ptr = out_ptr + SZ_OUT;
        soft_ptr = hard_ptr + SZ_HARD;
        mw_ptr   = soft_ptr + SZ_SOFT;
    }

    hard_kernel<<<NN, 32>>>(w_b, lptr, hard_ptr);

    fused_kernel<<<KK / ROWS, 256>>>(x, w_att, soft_ptr, out_ptr, mw_ptr);
}

// round 6
// speedup vs baseline: 1.2232x; 1.2232x over previous
#include <cuda_runtime.h>
#include <cuda_bf16.h>

// Problem shapes (fixed by dataset)
#define KK 2048   // batch/k dim
#define MM 512    // feature dim m
#define NN 64     // target dim n
#define EPSV 1e-8f
#define LMAX 32

// ---------------- scratch (static device globals; no allocation) ----------------
__device__ float g_S[KK * MM];     // logits x @ w_att
__device__ float g_soft[KK * MM];  // softmax fallback (used if out buffer small)
__device__ float g_hard[MM * NN];  // scores_hard fallback

// ---------------- Kernel 1: fp32 tiled GEMM  S = x @ w_att  (R1-proven) -----
#define BM 64
#define BN 64
#define BK 16
__global__ __launch_bounds__(256) void gemm_kernel(const float* __restrict__ A,
                                                   const float* __restrict__ B) {
    __shared__ float As[BK][BM + 4];
    __shared__ float Bs[BK][BN];

    const int t  = threadIdx.x;
    const int tx = t & 15;
    const int ty = t >> 4;
    const int bm = blockIdx.y * BM;
    const int bn = blockIdx.x * BN;

    const int arow = t >> 2;
    const int ac4  = (t & 3) << 2;
    const int brow = t >> 4;
    const int bc4  = (t & 15) << 2;

    float acc[4][4];
#pragma unroll
    for (int i = 0; i < 4; i++)
#pragma unroll
        for (int j = 0; j < 4; j++) acc[i][j] = 0.f;

    for (int kt = 0; kt < MM; kt += BK) {
        float4 av = *(const float4*)&A[(size_t)(bm + arow) * MM + kt + ac4];
        As[ac4 + 0][arow] = av.x;
        As[ac4 + 1][arow] = av.y;
        As[ac4 + 2][arow] = av.z;
        As[ac4 + 3][arow] = av.w;
        *(float4*)&Bs[brow][bc4] =
            *(const float4*)&B[(size_t)(kt + brow) * MM + bn + bc4];
        __syncthreads();

#pragma unroll
        for (int kk = 0; kk < BK; kk++) {
            float4 a = *(const float4*)&As[kk][ty << 2];
            float4 b = *(const float4*)&Bs[kk][tx << 2];
            acc[0][0] += a.x * b.x; acc[0][1] += a.x * b.y; acc[0][2] += a.x * b.z; acc[0][3] += a.x * b.w;
            acc[1][0] += a.y * b.x; acc[1][1] += a.y * b.y; acc[1][2] += a.y * b.z; acc[1][3] += a.y * b.w;
            acc[2][0] += a.z * b.x; acc[2][1] += a.z * b.y; acc[2][2] += a.z * b.z; acc[2][3] += a.z * b.w;
            acc[3][0] += a.w * b.x; acc[3][1] += a.w * b.y; acc[3][2] += a.w * b.z; acc[3][3] += a.w * b.w;
        }
        __syncthreads();
    }

#pragma unroll
    for (int i = 0; i < 4; i++) {
        float4 v = make_float4(acc[i][0], acc[i][1], acc[i][2], acc[i][3]);
        *(float4*)&g_S[(size_t)(bm + (ty << 2) + i) * MM + bn + (tx << 2)] = v;
    }
}

// ---------------- Kernel 2: row softmax (+EPS)  (R2-proven, single write) ----
__global__ __launch_bounds__(256) void softmax_kernel(float* __restrict__ dst) {
    const int k   = blockIdx.x;
    const int tid = threadIdx.x;
    const float* row = g_S + (size_t)k * MM;

    float v0 = row[tid];
    float v1 = row[tid + 256];

    __shared__ float red[256];
    red[tid] = fmaxf(v0, v1);
    __syncthreads();
#pragma unroll
    for (int s = 128; s > 0; s >>= 1) {
        if (tid < s) red[tid] = fmaxf(red[tid], red[tid + s]);
        __syncthreads();
    }
    float mx = red[0];
    __syncthreads();

    float e0 = __expf(v0 - mx);
    float e1 = __expf(v1 - mx);
    red[tid] = e0 + e1;
    __syncthreads();
#pragma unroll
    for (int s = 128; s > 0; s >>= 1) {
        if (tid < s) red[tid] += red[tid + s];
        __syncthreads();
    }
    float inv = 1.f / red[0];

    size_t base = (size_t)k * MM;
    dst[base + tid]       = e0 * inv + EPSV;
    dst[base + tid + 256] = e1 * inv + EPSV;
}

// ---------------- Kernel 3: per-column top-l + hard scores  (R3-proven) -----
__global__ __launch_bounds__(32) void hard_kernel(const float* __restrict__ wb,
                                                  const int* __restrict__ lptr,
                                                  float* __restrict__ dst) {
    const int n    = blockIdx.x;
    const int lane = threadIdx.x;
    int l = lptr ? *lptr : 8;
    if (l < 1) l = 1;
    if (l > LMAX) l = LMAX;

    float v[16];
#pragma unroll
    for (int i = 0; i < 16; i++)
        v[i] = wb[(lane * 16 + i) * NN + n];

    float top[LMAX];
    for (int i = 0; i < l; i++) top[i] = -3.4e38f;
#pragma unroll
    for (int i = 0; i < 16; i++) {
        float x = v[i];
        if (x > top[l - 1]) {
            int j = l - 1;
            while (j > 0 && top[j - 1] < x) { top[j] = top[j - 1]; j--; }
            top[j] = x;
        }
    }

    int ptr = 0;
    float thr = -3.4e38f;
    for (int r = 0; r < l; r++) {
        float cand = (ptr < l) ? top[ptr] : -3.4e38f;
        float m = cand;
#pragma unroll
        for (int off = 16; off > 0; off >>= 1)
            m = fmaxf(m, __shfl_xor_sync(0xffffffffu, m, off));
        unsigned b = __ballot_sync(0xffffffffu, cand == m);
        int src = __ffs(b) - 1;
        if (lane == src) ptr++;
        thr = m;
    }

#pragma unroll
    for (int i = 0; i < 16; i++) {
        float sh = v[i] - thr + EPSV;
        sh = fminf(fmaxf(sh, -1.f), 1.f);
        float h = (sh + 1.f) * 0.5f;
        dst[(lane * 16 + i) * NN + n] = h;
    }
}

// ---------------- Kernel 4: epilogue  (R2-proven EXACT geometry) ------------
// 16 threads per (k,m); each owns one float4 of n. Plain .wb stores.
__global__ __launch_bounds__(256) void epilogue_kernel(const float* __restrict__ x,
                                                       const float* __restrict__ soft,
                                                       const float* __restrict__ hard,
                                                       float* __restrict__ out,
                                                       float* __restrict__ mw) {
    const int idx = blockIdx.x * blockDim.x + threadIdx.x;  // 0 .. KK*MM*16-1
    const int n4  = idx & 15;
    const int km  = idx >> 4;       // 0 .. KK*MM-1
    const int m   = km & (MM - 1);

    float ss = __ldg(&soft[km]);
    float xv = __ldg(&x[km]);
    float4 h = __ldg((const float4*)(hard + m * NN + (n4 << 2)));

    float4 mw4 = make_float4(h.x * ss, h.y * ss, h.z * ss, h.w * ss);
    float4 o4  = make_float4(mw4.x * xv, mw4.y * xv, mw4.z * xv, mw4.w * xv);

    size_t base = (size_t)km * NN + (n4 << 2);
    *(float4*)&out[base] = o4;
    if (mw) *(float4*)&mw[base] = mw4;
}

// ---------------- launch ----------------
extern "C" void kernel_launch(void* const* d_in, const int* in_sizes, int n_in,
                              void* d_out, int out_size) {
    const float* x     = (const float*)d_in[0];
    const float* w_att = (const float*)d_in[1];
    const float* w_b   = (const float*)d_in[2];
    const int*   lptr  = (n_in > 3) ? (const int*)d_in[3] : nullptr;

    const long SZ_OUT  = (long)KK * MM * NN;
    const long SZ_HARD = (long)MM * NN;
    const long SZ_SOFT = (long)KK * MM;

    float* out_ptr = (float*)d_out;
    float* hard_dst;
    float* soft_dst;
    float* mw_ptr = nullptr;
    if ((long)out_size >= SZ_OUT + SZ_HARD + SZ_SOFT + SZ_OUT) {
        hard_dst = out_ptr + SZ_OUT;
        soft_dst = hard_dst + SZ_HARD;
        mw_ptr   = soft_dst + SZ_SOFT;
    } else {
        // fallback: harness only wants `out`; use scratch for intermediates
        float* dummy;
        cudaGetSymbolAddress((void**)&dummy, g_hard);
        hard_dst = dummy;
        cudaGetSymbolAddress((void**)&dummy, g_soft);
        soft_dst = dummy;
    }

    hard_kernel<<<NN, 32>>>(w_b, lptr, hard_dst);

    dim3 ggrid(MM / BN, KK / BM);
    gemm_kernel<<<ggrid, 256>>>(x, w_att);

    softmax_kernel<<<KK, 256>>>(soft_dst);

    int total = KK * MM * 16;
    epilogue_kernel<<<total / 256, 256>>>(x, soft_dst, hard_dst, out_ptr, mw_ptr);
}